// round 1
// baseline (speedup 1.0000x reference)
#include <cuda_runtime.h>
#include <cstdint>
#include <math.h>

#define DINLINE __device__ __forceinline__

constexpr int B_ = 256;
constexpr int C_ = 256;
constexpr int HW_ = 225;      // 15*15
constexpr int S_ = 8;
constexpr int NELEM = B_ * C_ * HW_;     // 14,745,600
constexpr int STATB = 4;                 // stat partial blocks (conv1x1 grid.y)
constexpr int UPD_BLOCKS = 15;           // update kernel grid.y

// ---------------- scratch (device globals; no allocation allowed) ----------
__device__ float g_concat[(size_t)B_ * 4 * C_ * HW_];  // 236 MB
__device__ float g_xc[NELEM];                          // 59 MB
__device__ float g_ybuf[NELEM];                        // 59 MB
__device__ float g_wft[4 * C_ * C_];
__device__ float g_w1t[C_ * C_];
__device__ float g_statsY[B_ * STATB * 2];
__device__ float g_stats2[B_ * UPD_BLOCKS * 2];

// ---------------- helpers --------------------------------------------------
DINLINE float elu_f(float v) { return v > 0.f ? v : expm1f(v); }

DINLINE uint32_t rotl32(uint32_t v, int s) { return __funnelshift_l(v, v, s); }

// Threefry-2x32, 20 rounds (JAX's threefry2x32 primitive)
DINLINE void threefry2x32(uint32_t k0, uint32_t k1, uint32_t& x0, uint32_t& x1) {
    uint32_t k2 = k0 ^ k1 ^ 0x1BD11BDAu;
    x0 += k0; x1 += k1;
#define TF_R(r) { x0 += x1; x1 = rotl32(x1, r); x1 ^= x0; }
    TF_R(13) TF_R(15) TF_R(26) TF_R(6)
    x0 += k1; x1 += k2 + 1u;
    TF_R(17) TF_R(29) TF_R(16) TF_R(24)
    x0 += k2; x1 += k0 + 2u;
    TF_R(13) TF_R(15) TF_R(26) TF_R(6)
    x0 += k0; x1 += k1 + 3u;
    TF_R(17) TF_R(29) TF_R(16) TF_R(24)
    x0 += k1; x1 += k2 + 4u;
    TF_R(13) TF_R(15) TF_R(26) TF_R(6)
    x0 += k2; x1 += k0 + 5u;
#undef TF_R
}

// ---------------- weight transpose ([CO][CI] -> [CI][CO]) ------------------
__global__ void transpose_kernel(const float* __restrict__ w, float* __restrict__ wt, int K) {
    int idx = blockIdx.x * 256 + threadIdx.x;
    if (idx < C_ * K) {
        int co = idx / K;
        int ci = idx % K;
        wt[ci * C_ + co] = w[idx];
    }
}

// ---------------- multi-tap direct conv + ELU -> concat buffer --------------
// block: one batch b, 32 output channels. 256 threads = 16 rows x 16 ch-slots,
// each thread does 2 output channels (cg, cg+16) x 15 pixels of its row.
template <int KH, int KW, int DIL, int PAD>
__global__ void __launch_bounds__(256)
conv_elu_kernel(const float* __restrict__ x,      // [B,256,15,15]
                const float* __restrict__ w,      // [256,256,KH,KW]
                const float* __restrict__ bias,   // [256]
                int co_off)                       // channel offset in concat
{
    constexpr int P = 15 + 2 * PAD;               // padded plane size
    constexpr int TAPS = KH * KW;
    constexpr int CI_CHUNK = 4;
    constexpr int RW = 15 + (KW - 1) * DIL;       // row register width

    __shared__ float sp[CI_CHUNK][P][P];
    __shared__ float sw[CI_CHUNK][32][TAPS];

    int b = blockIdx.x;
    int co_base = blockIdx.y * 32;
    int t = threadIdx.x;
    int r = t & 15;          // output row (0..14 active)
    int cg = t >> 4;         // 0..15

    float acc[2][15];
    {
        float b0 = bias[co_base + cg];
        float b1v = bias[co_base + cg + 16];
#pragma unroll
        for (int p = 0; p < 15; p++) { acc[0][p] = b0; acc[1][p] = b1v; }
    }

    const float* xb = x + (size_t)b * C_ * HW_;

    for (int ci0 = 0; ci0 < C_; ci0 += CI_CHUNK) {
        __syncthreads();
        // stage padded input patch for CI_CHUNK channels
        constexpr int PATCH = CI_CHUNK * P * P;
        for (int idx = t; idx < PATCH; idx += 256) {
            int ci = idx / (P * P);
            int rem = idx - ci * (P * P);
            int py = rem / P - PAD;
            int px = rem - (rem / P) * P - PAD;
            float v = 0.f;
            if (py >= 0 && py < 15 && px >= 0 && px < 15)
                v = xb[(ci0 + ci) * HW_ + py * 15 + px];
            ((float*)sp)[idx] = v;
        }
        // stage weights: sw[ci][c][tap] = w[(co_base+c)*C + ci0+ci][tap]
        constexpr int WCNT = CI_CHUNK * 32 * TAPS;
        for (int idx = t; idx < WCNT; idx += 256) {
            int c2 = idx / (CI_CHUNK * TAPS);
            int rem = idx - c2 * (CI_CHUNK * TAPS);
            int ci = rem / TAPS;
            int tap = rem - ci * TAPS;
            sw[ci][c2][tap] = w[((size_t)(co_base + c2) * C_ + (ci0 + ci)) * TAPS + tap];
        }
        __syncthreads();
        if (r < 15) {
#pragma unroll
            for (int ci = 0; ci < CI_CHUNK; ci++) {
#pragma unroll
                for (int ky = 0; ky < KH; ky++) {
                    float rv[RW];
                    const float* prow = &sp[ci][r + ky * DIL][0];
#pragma unroll
                    for (int u = 0; u < RW; u++) rv[u] = prow[u];
#pragma unroll
                    for (int kx = 0; kx < KW; kx++) {
                        float w0 = sw[ci][cg][ky * KW + kx];
                        float w1 = sw[ci][cg + 16][ky * KW + kx];
#pragma unroll
                        for (int px = 0; px < 15; px++) {
                            acc[0][px] = fmaf(rv[px + kx * DIL], w0, acc[0][px]);
                            acc[1][px] = fmaf(rv[px + kx * DIL], w1, acc[1][px]);
                        }
                    }
                }
            }
        }
    }

    if (r < 15) {
#pragma unroll
        for (int j = 0; j < 2; j++) {
            int co = co_base + cg + 16 * j;
            float* o = g_concat + ((size_t)b * (4 * C_) + co_off + co) * HW_ + r * 15;
#pragma unroll
            for (int px = 0; px < 15; px++) o[px] = elu_f(acc[j][px]);
        }
    }
}

// ---------------- 1x1 conv (per-batch GEMM), optional ELU / stats -----------
// block: one batch b, 64 output channels. 256 threads = 16 rows x 16 slots,
// 4 co per thread (cg, cg+16, cg+32, cg+48).
template <int K, bool DO_ELU, bool DO_STATS>
__global__ void __launch_bounds__(256)
conv1x1_kernel(const float* __restrict__ in,    // [B,K,225]
               const float* __restrict__ wt,    // [K,256] (ci-major)
               const float* __restrict__ bias,  // [256]
               float* __restrict__ out,         // [B,256,225]
               float* __restrict__ stats)       // [B][STATB][2] (pre-activation)
{
    __shared__ float sin_[16][225];
    __shared__ float sw[16][64];
    __shared__ float red[256];

    int b = blockIdx.x;
    int co_base = blockIdx.y * 64;
    int t = threadIdx.x;
    int r = t & 15;
    int cg = t >> 4;

    float acc[4][15];
#pragma unroll
    for (int j = 0; j < 4; j++) {
        float bv = bias[co_base + cg + 16 * j];
#pragma unroll
        for (int p = 0; p < 15; p++) acc[j][p] = bv;
    }

    const float* inb = in + (size_t)b * K * HW_;

    for (int ci0 = 0; ci0 < K; ci0 += 16) {
        __syncthreads();
        for (int idx = t; idx < 16 * 225; idx += 256) {
            int ci = idx / 225;
            int p = idx - ci * 225;
            sin_[ci][p] = inb[(ci0 + ci) * HW_ + p];
        }
        for (int idx = t; idx < 16 * 64; idx += 256) {
            int ci = idx >> 6;
            int c = idx & 63;
            sw[ci][c] = wt[(size_t)(ci0 + ci) * C_ + co_base + c];
        }
        __syncthreads();
        if (r < 15) {
#pragma unroll
            for (int ci = 0; ci < 16; ci++) {
                float rv[15];
#pragma unroll
                for (int u = 0; u < 15; u++) rv[u] = sin_[ci][r * 15 + u];
                float w0 = sw[ci][cg], w1 = sw[ci][cg + 16];
                float w2 = sw[ci][cg + 32], w3 = sw[ci][cg + 48];
#pragma unroll
                for (int u = 0; u < 15; u++) {
                    acc[0][u] = fmaf(rv[u], w0, acc[0][u]);
                    acc[1][u] = fmaf(rv[u], w1, acc[1][u]);
                    acc[2][u] = fmaf(rv[u], w2, acc[2][u]);
                    acc[3][u] = fmaf(rv[u], w3, acc[3][u]);
                }
            }
        }
    }

    float s1 = 0.f, s2 = 0.f;
    if (r < 15) {
#pragma unroll
        for (int j = 0; j < 4; j++) {
            int co = co_base + cg + 16 * j;
            float* o = out + ((size_t)b * C_ + co) * HW_ + r * 15;
#pragma unroll
            for (int u = 0; u < 15; u++) {
                float v = acc[j][u];
                if (DO_STATS) { s1 += v; s2 = fmaf(v, v, s2); }
                o[u] = DO_ELU ? elu_f(v) : v;
            }
        }
    }
    if (DO_STATS) {
        __syncthreads();
        red[t] = s1; __syncthreads();
        for (int off = 128; off > 0; off >>= 1) {
            if (t < off) red[t] += red[t + off];
            __syncthreads();
        }
        if (t == 0) stats[((size_t)b * STATB + blockIdx.y) * 2 + 0] = red[0];
        __syncthreads();
        red[t] = s2; __syncthreads();
        for (int off = 128; off > 0; off >>= 1) {
            if (t < off) red[t] += red[t + off];
            __syncthreads();
        }
        if (t == 0) stats[((size_t)b * STATB + blockIdx.y) * 2 + 1] = red[0];
    }
}

// ---------------- per-step update: LN + ELU + noise + residual --------------
__global__ void __launch_bounds__(256)
step_update_kernel(const float* __restrict__ ybuf,
                   const float* __restrict__ lnw,
                   const float* __restrict__ lnb,
                   const float* __restrict__ xin,
                   float* __restrict__ xout,
                   const float* __restrict__ sp_arr,
                   const float* __restrict__ ss_arr,
                   const float* __restrict__ rw_arr,
                   const float* __restrict__ prob_arr,
                   int step)
{
    int b = blockIdx.x;
    int t = threadIdx.x;

    // LN stats over (C,H,W) for this batch (biased var, as jnp.var default)
    double sum = 0.0, sumsq = 0.0;
#pragma unroll
    for (int k = 0; k < STATB; k++) {
        sum   += (double)g_statsY[(b * STATB + k) * 2 + 0];
        sumsq += (double)g_statsY[(b * STATB + k) * 2 + 1];
    }
    const double n = (double)(C_ * HW_);
    double mu_d = sum / n;
    double var_d = sumsq / n - mu_d * mu_d;
    float mu = (float)mu_d;
    float rs = (float)(1.0 / sqrt(var_d + 1e-5));

    float sp = sp_arr[step];
    float ss = ss_arr[step];
    float rw = rw_arr[step];
    float prob = prob_arr[step];
    float cns = prob * ss;
    float rw1 = 1.f + rw;

    // fold_in(key(42), step) -> per-step key
    uint32_t fk0 = 0u, fk1 = (uint32_t)step;
    threefry2x32(0u, 42u, fk0, fk1);

    int q0 = blockIdx.y * 3840 + t * 15;
    size_t base = (size_t)b * (C_ * HW_) + q0;

    float s1 = 0.f, s2 = 0.f;
#pragma unroll
    for (int e = 0; e < 15; e++) {
        int q = q0 + e;
        float y = ybuf[base + e];
        float d = (y - mu) * rs;
        d = fmaf(d, lnw[q], lnb[q]);
        d = elu_f(d);
        s1 += d; s2 = fmaf(d, d, s2);
        // partitionable threefry random bits: counts64 hi=0, lo=flat index
        uint32_t c0 = 0u, c1 = (uint32_t)(base + e);
        threefry2x32(fk0, fk1, c0, c1);
        uint32_t bits = c0 ^ c1;
        float u = __uint_as_float(0x3f800000u | (bits >> 9)) - 1.0f;
        float xc = xin[base + e];
        xout[base + e] = fmaf(xc, rw1, fmaf(d, sp, u * cns));
    }

    __shared__ float red[256];
    red[t] = s1; __syncthreads();
    for (int off = 128; off > 0; off >>= 1) {
        if (t < off) red[t] += red[t + off];
        __syncthreads();
    }
    if (t == 0) g_stats2[(b * UPD_BLOCKS + blockIdx.y) * 2 + 0] = red[0];
    __syncthreads();
    red[t] = s2; __syncthreads();
    for (int off = 128; off > 0; off >>= 1) {
        if (t < off) red[t] += red[t + off];
        __syncthreads();
    }
    if (t == 0) g_stats2[(b * UPD_BLOCKS + blockIdx.y) * 2 + 1] = red[0];
}

// ---------------- finalize per-step unbiased variance -----------------------
__global__ void var_final_kernel(float* __restrict__ out_var, int step) {
    int b = threadIdx.x;  // 256 threads
    double s1 = 0.0, s2 = 0.0;
    for (int k = 0; k < UPD_BLOCKS; k++) {
        s1 += (double)g_stats2[(b * UPD_BLOCKS + k) * 2 + 0];
        s2 += (double)g_stats2[(b * UPD_BLOCKS + k) * 2 + 1];
    }
    const double n = (double)(C_ * HW_);
    double v = (s2 - s1 * s1 / n) / (n - 1.0);
    out_var[b * S_ + step] = (float)v;
}

// ---------------- launch ----------------------------------------------------
extern "C" void kernel_launch(void* const* d_in, const int* in_sizes, int n_in,
                              void* d_out, int out_size) {
    const float* x    = (const float*)d_in[0];
    const float* prob = (const float*)d_in[1];
    const float* w3   = (const float*)d_in[2];
    const float* b3   = (const float*)d_in[3];
    const float* w3d  = (const float*)d_in[4];
    const float* b3d  = (const float*)d_in[5];
    const float* w5   = (const float*)d_in[6];
    const float* b5   = (const float*)d_in[7];
    const float* w7   = (const float*)d_in[8];
    const float* b7   = (const float*)d_in[9];
    const float* wf   = (const float*)d_in[10];
    const float* bf   = (const float*)d_in[11];
    const float* w1   = (const float*)d_in[12];
    const float* b1   = (const float*)d_in[13];
    const float* lnw  = (const float*)d_in[14];
    const float* lnb  = (const float*)d_in[15];
    const float* spar = (const float*)d_in[16];
    const float* ssc  = (const float*)d_in[17];
    const float* rwv  = (const float*)d_in[18];

    float* out = (float*)d_out;
    float* out_var = out + (size_t)NELEM;

    float *concat, *xc, *ybuf, *wft, *w1t, *statsY;
    cudaGetSymbolAddress((void**)&concat, g_concat);
    cudaGetSymbolAddress((void**)&xc, g_xc);
    cudaGetSymbolAddress((void**)&ybuf, g_ybuf);
    cudaGetSymbolAddress((void**)&wft, g_wft);
    cudaGetSymbolAddress((void**)&w1t, g_w1t);
    cudaGetSymbolAddress((void**)&statsY, g_statsY);

    // transpose fusion + step weights to [ci][co]
    transpose_kernel<<<(C_ * 4 * C_ + 255) / 256, 256>>>(wf, wft, 4 * C_);
    transpose_kernel<<<(C_ * C_ + 255) / 256, 256>>>(w1, w1t, C_);

    // multi-scale perception -> g_concat
    dim3 gconv(B_, 8);
    conv_elu_kernel<3, 3, 1, 1><<<gconv, 256>>>(x, w3, b3, 0);
    conv_elu_kernel<3, 3, 2, 2><<<gconv, 256>>>(x, w3d, b3d, 256);
    conv_elu_kernel<5, 5, 1, 2><<<gconv, 256>>>(x, w5, b5, 512);
    conv_elu_kernel<7, 7, 1, 3><<<gconv, 256>>>(x, w7, b7, 768);

    // fusion 1x1 (4C -> C) + ELU -> g_xc
    conv1x1_kernel<1024, true, false><<<dim3(B_, STATB), 256>>>(concat, wft, bf, xc, nullptr);

    // 8 NCA steps
    for (int i = 0; i < S_; i++) {
        conv1x1_kernel<256, false, true><<<dim3(B_, STATB), 256>>>(xc, w1t, b1, ybuf, statsY);
        float* xo = (i == S_ - 1) ? out : xc;
        step_update_kernel<<<dim3(B_, UPD_BLOCKS), 256>>>(ybuf, lnw, lnb, xc, xo,
                                                          spar, ssc, rwv, prob, i);
        var_final_kernel<<<1, 256>>>(out_var, i);
    }
}